// round 9
// baseline (speedup 1.0000x reference)
#include <cuda_runtime.h>
#include <math.h>

#define N_COLS 4096
#define TPB    128
#define NW     (TPB / 32)
#define EPS    1e-14f

// One 128-thread block per row, 8 float4 per thread -> 16 front-batched
// LDG.128 per thread (max per-warp MLP tried so far), fused ||v||^2,
// ONE barrier per block, v/bias reloaded from L1 in the epilogue.
// out[i] = x[i] - (2*(x.v)/(||v||+eps)^2) * v[i] + bias[i]
__global__ void __launch_bounds__(TPB, 8)
householder_kernel(const float* __restrict__ x,
                   const float* __restrict__ v,
                   const float* __restrict__ bias,
                   float* __restrict__ out) {
    const int tid = threadIdx.x;
    const int w = tid >> 5, l = tid & 31;
    const int row = blockIdx.x;

    const float4* __restrict__ xr = (const float4*)(x + (size_t)row * N_COLS);
    const float4* __restrict__ vr = (const float4*)v;
    const float4* __restrict__ br = (const float4*)bias;
    float4* __restrict__       orow = (float4*)(out + (size_t)row * N_COLS);

    __shared__ float red_d[NW];
    __shared__ float red_n[NW];

    // ---- single pass: load row + v, accumulate dot and ||v||^2 ----
    float4 xv[8];
    float dot = 0.0f, vn = 0.0f;
    #pragma unroll
    for (int j = 0; j < 8; j++) {
        const int idx = tid + j * TPB;     // coalesced 128B per warp
        xv[j] = xr[idx];
        float4 t = vr[idx];                // L1/L2 broadcast-hot (16KB)
        dot = fmaf(xv[j].x, t.x, dot);
        dot = fmaf(xv[j].y, t.y, dot);
        dot = fmaf(xv[j].z, t.z, dot);
        dot = fmaf(xv[j].w, t.w, dot);
        vn  = fmaf(t.x, t.x, vn);
        vn  = fmaf(t.y, t.y, vn);
        vn  = fmaf(t.z, t.z, vn);
        vn  = fmaf(t.w, t.w, vn);
    }

    #pragma unroll
    for (int o = 16; o > 0; o >>= 1) {
        dot += __shfl_xor_sync(0xffffffffu, dot, o);
        vn  += __shfl_xor_sync(0xffffffffu, vn,  o);
    }
    if (l == 0) { red_d[w] = dot; red_n[w] = vn; }
    __syncthreads();                        // the ONLY barrier (4 warps)

    // every thread finishes the reduction itself (broadcast LDS)
    float td = 0.0f, tn = 0.0f;
    #pragma unroll
    for (int i = 0; i < NW; i++) { td += red_d[i]; tn += red_n[i]; }
    const float s = 1.0f / (sqrtf(tn) + EPS);
    const float coef = 2.0f * td * s * s;

    // ---- epilogue: reload v (L1-hot) + bias, fuse, store ----
    #pragma unroll
    for (int j = 0; j < 8; j++) {
        const int idx = tid + j * TPB;
        float4 vvj = vr[idx];
        float4 bb  = br[idx];
        float4 o4;
        o4.x = fmaf(-coef, vvj.x, xv[j].x) + bb.x;
        o4.y = fmaf(-coef, vvj.y, xv[j].y) + bb.y;
        o4.z = fmaf(-coef, vvj.z, xv[j].z) + bb.z;
        o4.w = fmaf(-coef, vvj.w, xv[j].w) + bb.w;
        orow[idx] = o4;
    }
}

extern "C" void kernel_launch(void* const* d_in, const int* in_sizes, int n_in,
                              void* d_out, int out_size) {
    const float* x    = (const float*)d_in[0];   // [16384, 4096]
    const float* v    = (const float*)d_in[1];   // [4096, 1]
    const float* bias = (const float*)d_in[2];   // [4096]
    float* out = (float*)d_out;

    const int n_rows = in_sizes[0] / N_COLS;     // 16384

    householder_kernel<<<n_rows, TPB>>>(x, v, bias, out);
}

// round 10
// speedup vs baseline: 1.1436x; 1.1436x over previous
#include <cuda_runtime.h>
#include <math.h>

#define N_COLS 4096
#define TPB    256
#define EPS    1e-14f

// Final configuration (measured best across 9 rounds; at the B300 LTS cap):
// one 256-thread block per row, 4 float4 per thread (8 front-batched LDG.128
// incl. v -> optimal L1tex queue depth), fused ||v||^2, ONE barrier per
// block, v/bias reloaded from L1 in the epilogue (48 regs, 5 blocks/SM).
// out[i] = x[i] - (2*(x.v)/(||v||+eps)^2) * v[i] + bias[i]
__global__ void __launch_bounds__(TPB, 5)
householder_kernel(const float* __restrict__ x,
                   const float* __restrict__ v,
                   const float* __restrict__ bias,
                   float* __restrict__ out) {
    const int tid = threadIdx.x;
    const int w = tid >> 5, l = tid & 31;
    const int row = blockIdx.x;

    const float4* __restrict__ xr = (const float4*)(x + (size_t)row * N_COLS);
    const float4* __restrict__ vr = (const float4*)v;
    const float4* __restrict__ br = (const float4*)bias;
    float4* __restrict__       orow = (float4*)(out + (size_t)row * N_COLS);

    __shared__ float red_d[TPB / 32];
    __shared__ float red_n[TPB / 32];

    // ---- single pass: load row + v, accumulate dot and ||v||^2 ----
    float4 xv[4];
    float dot = 0.0f, vn = 0.0f;
    #pragma unroll
    for (int j = 0; j < 4; j++) {
        const int idx = tid + j * TPB;     // coalesced 128B per warp
        xv[j] = xr[idx];
        float4 t = vr[idx];                // L1/L2 broadcast-hot (16KB)
        dot = fmaf(xv[j].x, t.x, dot);
        dot = fmaf(xv[j].y, t.y, dot);
        dot = fmaf(xv[j].z, t.z, dot);
        dot = fmaf(xv[j].w, t.w, dot);
        vn  = fmaf(t.x, t.x, vn);
        vn  = fmaf(t.y, t.y, vn);
        vn  = fmaf(t.z, t.z, vn);
        vn  = fmaf(t.w, t.w, vn);
    }

    #pragma unroll
    for (int o = 16; o > 0; o >>= 1) {
        dot += __shfl_xor_sync(0xffffffffu, dot, o);
        vn  += __shfl_xor_sync(0xffffffffu, vn,  o);
    }
    if (l == 0) { red_d[w] = dot; red_n[w] = vn; }
    __syncthreads();                        // the ONLY barrier

    // every thread finishes the reduction itself (broadcast LDS = conflict-free)
    float td = 0.0f, tn = 0.0f;
    #pragma unroll
    for (int i = 0; i < TPB / 32; i++) { td += red_d[i]; tn += red_n[i]; }
    const float s = 1.0f / (sqrtf(tn) + EPS);
    const float coef = 2.0f * td * s * s;

    // ---- epilogue: reload v (L1-hot) + bias, fuse, store ----
    #pragma unroll
    for (int j = 0; j < 4; j++) {
        const int idx = tid + j * TPB;
        float4 vvj = vr[idx];
        float4 bb  = br[idx];
        float4 o4;
        o4.x = fmaf(-coef, vvj.x, xv[j].x) + bb.x;
        o4.y = fmaf(-coef, vvj.y, xv[j].y) + bb.y;
        o4.z = fmaf(-coef, vvj.z, xv[j].z) + bb.z;
        o4.w = fmaf(-coef, vvj.w, xv[j].w) + bb.w;
        orow[idx] = o4;
    }
}

extern "C" void kernel_launch(void* const* d_in, const int* in_sizes, int n_in,
                              void* d_out, int out_size) {
    const float* x    = (const float*)d_in[0];   // [16384, 4096]
    const float* v    = (const float*)d_in[1];   // [4096, 1]
    const float* bias = (const float*)d_in[2];   // [4096]
    float* out = (float*)d_out;

    const int n_rows = in_sizes[0] / N_COLS;     // 16384

    householder_kernel<<<n_rows, TPB>>>(x, v, bias, out);
}

// round 11
// speedup vs baseline: 1.1616x; 1.0158x over previous
#include <cuda_runtime.h>
#include <math.h>

#define N_COLS 4096
#define TPB    256
#define EPS    1e-14f

// Measured-best shape (256 thr/row, 4 float4/thread, fused ||v||^2, one
// barrier, v/bias reloaded from L1) + streaming cache policy on the two
// 256MB single-use streams: __ldcs on x, __stcs on out. v/bias keep the
// default caching policy so their hot lines survive in L1/L2.
// out[i] = x[i] - (2*(x.v)/(||v||+eps)^2) * v[i] + bias[i]
__global__ void __launch_bounds__(TPB, 5)
householder_kernel(const float* __restrict__ x,
                   const float* __restrict__ v,
                   const float* __restrict__ bias,
                   float* __restrict__ out) {
    const int tid = threadIdx.x;
    const int w = tid >> 5, l = tid & 31;
    const int row = blockIdx.x;

    const float4* __restrict__ xr = (const float4*)(x + (size_t)row * N_COLS);
    const float4* __restrict__ vr = (const float4*)v;
    const float4* __restrict__ br = (const float4*)bias;
    float4* __restrict__       orow = (float4*)(out + (size_t)row * N_COLS);

    __shared__ float red_d[TPB / 32];
    __shared__ float red_n[TPB / 32];

    // ---- single pass: load row + v, accumulate dot and ||v||^2 ----
    float4 xv[4];
    float dot = 0.0f, vn = 0.0f;
    #pragma unroll
    for (int j = 0; j < 4; j++) {
        const int idx = tid + j * TPB;     // coalesced 128B per warp
        xv[j] = __ldcs(&xr[idx]);          // streaming: x is single-use
        float4 t = vr[idx];                // default policy: v is L1/L2-hot
        dot = fmaf(xv[j].x, t.x, dot);
        dot = fmaf(xv[j].y, t.y, dot);
        dot = fmaf(xv[j].z, t.z, dot);
        dot = fmaf(xv[j].w, t.w, dot);
        vn  = fmaf(t.x, t.x, vn);
        vn  = fmaf(t.y, t.y, vn);
        vn  = fmaf(t.z, t.z, vn);
        vn  = fmaf(t.w, t.w, vn);
    }

    #pragma unroll
    for (int o = 16; o > 0; o >>= 1) {
        dot += __shfl_xor_sync(0xffffffffu, dot, o);
        vn  += __shfl_xor_sync(0xffffffffu, vn,  o);
    }
    if (l == 0) { red_d[w] = dot; red_n[w] = vn; }
    __syncthreads();                        // the ONLY barrier

    // every thread finishes the reduction itself (broadcast LDS = conflict-free)
    float td = 0.0f, tn = 0.0f;
    #pragma unroll
    for (int i = 0; i < TPB / 32; i++) { td += red_d[i]; tn += red_n[i]; }
    const float s = 1.0f / (sqrtf(tn) + EPS);
    const float coef = 2.0f * td * s * s;

    // ---- epilogue: reload v (L1-hot) + bias, fuse, streaming store ----
    #pragma unroll
    for (int j = 0; j < 4; j++) {
        const int idx = tid + j * TPB;
        float4 vvj = vr[idx];
        float4 bb  = br[idx];
        float4 o4;
        o4.x = fmaf(-coef, vvj.x, xv[j].x) + bb.x;
        o4.y = fmaf(-coef, vvj.y, xv[j].y) + bb.y;
        o4.z = fmaf(-coef, vvj.z, xv[j].z) + bb.z;
        o4.w = fmaf(-coef, vvj.w, xv[j].w) + bb.w;
        __stcs(&orow[idx], o4);            // streaming: out never re-read
    }
}

extern "C" void kernel_launch(void* const* d_in, const int* in_sizes, int n_in,
                              void* d_out, int out_size) {
    const float* x    = (const float*)d_in[0];   // [16384, 4096]
    const float* v    = (const float*)d_in[1];   // [4096, 1]
    const float* bias = (const float*)d_in[2];   // [4096]
    float* out = (float*)d_out;

    const int n_rows = in_sizes[0] / N_COLS;     // 16384

    householder_kernel<<<n_rows, TPB>>>(x, v, bias, out);
}

// round 12
// speedup vs baseline: 1.1736x; 1.0104x over previous
#include <cuda_runtime.h>
#include <math.h>

#define N_COLS 4096
#define TPB    256
#define EPS    1e-14f

// Best-measured shape + v staged in shared memory:
//   - 256 thr/row, 4 float4/thread, fused ||v||^2, ONE barrier
//   - __ldcs on x, __stcs on out (single-use 256MB streams)
//   - v stored to smem during the dot pass (STS drained by the barrier),
//     epilogue reads it via LDS -> 4 fewer LDG.128/thread competing with
//     the streaming x/out traffic in the L1tex queue.
// out[i] = x[i] - (2*(x.v)/(||v||+eps)^2) * v[i] + bias[i]
__global__ void __launch_bounds__(TPB, 5)
householder_kernel(const float* __restrict__ x,
                   const float* __restrict__ v,
                   const float* __restrict__ bias,
                   float* __restrict__ out) {
    const int tid = threadIdx.x;
    const int w = tid >> 5, l = tid & 31;
    const int row = blockIdx.x;

    const float4* __restrict__ xr = (const float4*)(x + (size_t)row * N_COLS);
    const float4* __restrict__ vr = (const float4*)v;
    const float4* __restrict__ br = (const float4*)bias;
    float4* __restrict__       orow = (float4*)(out + (size_t)row * N_COLS);

    __shared__ float4 vtile[N_COLS / 4];      // 16 KB
    __shared__ float  red_d[TPB / 32];
    __shared__ float  red_n[TPB / 32];

    // ---- single pass: load row + v, stage v to smem, accumulate dots ----
    float4 xv[4];
    float dot = 0.0f, vn = 0.0f;
    #pragma unroll
    for (int j = 0; j < 4; j++) {
        const int idx = tid + j * TPB;        // coalesced 128B per warp
        xv[j] = __ldcs(&xr[idx]);             // streaming: x is single-use
        float4 t = vr[idx];                   // default policy: v is L2-hot
        vtile[idx] = t;                       // STS, drained by the barrier
        dot = fmaf(xv[j].x, t.x, dot);
        dot = fmaf(xv[j].y, t.y, dot);
        dot = fmaf(xv[j].z, t.z, dot);
        dot = fmaf(xv[j].w, t.w, dot);
        vn  = fmaf(t.x, t.x, vn);
        vn  = fmaf(t.y, t.y, vn);
        vn  = fmaf(t.z, t.z, vn);
        vn  = fmaf(t.w, t.w, vn);
    }

    #pragma unroll
    for (int o = 16; o > 0; o >>= 1) {
        dot += __shfl_xor_sync(0xffffffffu, dot, o);
        vn  += __shfl_xor_sync(0xffffffffu, vn,  o);
    }
    if (l == 0) { red_d[w] = dot; red_n[w] = vn; }
    __syncthreads();                           // orders STS + partials

    // every thread finishes the reduction itself (broadcast LDS)
    float td = 0.0f, tn = 0.0f;
    #pragma unroll
    for (int i = 0; i < TPB / 32; i++) { td += red_d[i]; tn += red_n[i]; }
    const float s = 1.0f / (sqrtf(tn) + EPS);
    const float coef = 2.0f * td * s * s;

    // ---- epilogue: v from smem (LDS), bias from L1, streaming store ----
    #pragma unroll
    for (int j = 0; j < 4; j++) {
        const int idx = tid + j * TPB;
        float4 vvj = vtile[idx];               // LDS, conflict-free
        float4 bb  = br[idx];
        float4 o4;
        o4.x = fmaf(-coef, vvj.x, xv[j].x) + bb.x;
        o4.y = fmaf(-coef, vvj.y, xv[j].y) + bb.y;
        o4.z = fmaf(-coef, vvj.z, xv[j].z) + bb.z;
        o4.w = fmaf(-coef, vvj.w, xv[j].w) + bb.w;
        __stcs(&orow[idx], o4);                // streaming: out never re-read
    }
}

extern "C" void kernel_launch(void* const* d_in, const int* in_sizes, int n_in,
                              void* d_out, int out_size) {
    const float* x    = (const float*)d_in[0];   // [16384, 4096]
    const float* v    = (const float*)d_in[1];   // [4096, 1]
    const float* bias = (const float*)d_in[2];   // [4096]
    float* out = (float*)d_out;

    const int n_rows = in_sizes[0] / N_COLS;     // 16384

    householder_kernel<<<n_rows, TPB>>>(x, v, bias, out);
}